// round 14
// baseline (speedup 1.0000x reference)
#include <cuda_runtime.h>
#include <cuda_bf16.h>
#include <cstdint>

#define TPB 512
#define NPS 10
#define O_W1UH 0
#define O_W1UL 32768
#define O_W2H  65536
#define O_W2L  98304
#define O_X    131072
#define O_W1XL 163840
#define O_SCRA 196608
#define O_SCRB 213504
#define O_B1   230400
#define SMEM_TOTAL 231424

__device__ __forceinline__ uint32_t s2u(const void* p){
  uint32_t a; asm("{ .reg .u64 t; cvta.to.shared.u64 t,%1; cvt.u32.u64 %0,t; }":"=r"(a):"l"(p)); return a;
}
__device__ __forceinline__ uint32_t pk2(float lo, float hi){
  uint32_t r; asm("cvt.rn.bf16x2.f32 %0,%1,%2;":"=r"(r):"f"(hi),"f"(lo)); return r;
}
__device__ __forceinline__ void pkhl(float a, float b, uint32_t& h, uint32_t& l){
  h = pk2(a, b);
  float ah = __uint_as_float(h << 16), bh = __uint_as_float(h & 0xffff0000u);
  l = pk2(a - ah, b - bh);
}
__device__ __forceinline__ int swo(int r, int cb){ return r*128 + (cb ^ ((r&7)<<4)); }

#define MMA(d,a,b0,b1) asm volatile( \
  "mma.sync.aligned.m16n8k16.row.col.f32.bf16.bf16.f32 {%0,%1,%2,%3},{%4,%5,%6,%7},{%8,%9},{%0,%1,%2,%3};" \
  :"+f"((d)[0]),"+f"((d)[1]),"+f"((d)[2]),"+f"((d)[3]) \
  :"r"((a)[0]),"r"((a)[1]),"r"((a)[2]),"r"((a)[3]),"r"(b0),"r"(b1))
#define LDSM(r0,r1,r2,r3,ad) asm volatile( \
  "ldmatrix.sync.aligned.m8n8.x4.shared.b16 {%0,%1,%2,%3},[%4];" \
  :"=r"(r0),"=r"(r1),"=r"(r2),"=r"(r3):"r"(ad))
#define LDSMT(r0,r1,r2,r3,ad) asm volatile( \
  "ldmatrix.sync.aligned.m8n8.x4.trans.shared.b16 {%0,%1,%2,%3},[%4];" \
  :"=r"(r0),"=r"(r1),"=r"(r2),"=r"(r3):"r"(ad))

// p[m, q-quarter 64h] = A(aH/aL, k=64) @ W2^T   (plain ldmatrix on [h][d] tile)
#define PGEMM() do { \
  _Pragma("unroll") for (int i_=0;i_<32;i_++) p[i_]=0.f; \
  _Pragma("unroll") for (int j_=0;j_<4;j_++){ \
    _Pragma("unroll") for (int tp_=0;tp_<4;tp_++){ int hb_=hq+16*tp_; \
      uint32_t b0,b1r,b2,b3,c0,c1,c2,c3; \
      LDSM(b0,b1r,b2,b3, smb+O_W2H+swo(hb_+prow,32*j_+pcol)); \
      LDSM(c0,c1,c2,c3, smb+O_W2L+swo(hb_+prow,32*j_+pcol)); \
      MMA(p+8*tp_,  aH+4*j_,b0,b1r); MMA(p+8*tp_+4,aH+4*j_,b2,b3); \
      MMA(p+8*tp_,  aL+4*j_,b0,b1r); MMA(p+8*tp_+4,aL+4*j_,b2,b3); \
      MMA(p+8*tp_,  aH+4*j_,c0,c1);  MMA(p+8*tp_+4,aH+4*j_,c2,c3); \
  } } } while(0)

// one k-chunk (16 h of own quarter) of the d=64 GEMM (trans B)
#define WCHUNK(BH,BL,J2,YH,YL) do { int kb_=hq+16*(J2); \
  _Pragma("unroll") for (int np_=0;np_<4;np_++){ \
    uint32_t b0,b1r,b2,b3,c0,c1,c2,c3; \
    LDSMT(b0,b1r,b2,b3, smb+(BH)+swo(kb_+trow,32*np_+tcol)); \
    LDSMT(c0,c1,c2,c3, smb+(BL)+swo(kb_+trow,32*np_+tcol)); \
    MMA(w+8*np_,  YH,b0,b1r); MMA(w+8*np_+4,YH,b2,b3); \
    MMA(w+8*np_,  YL,b0,b1r); MMA(w+8*np_+4,YL,b2,b3); \
    MMA(w+8*np_,  YH,c0,c1);  MMA(w+8*np_+4,YH,c2,c3); \
  } } while(0)

#define SCR_ST(SB) do { _Pragma("unroll") for (int nt=0;nt<8;nt++){ int col=8*nt+2*tig; \
  *(float2*)((SB)+rl*66+col)     = make_float2(w[4*nt],  w[4*nt+1]); \
  *(float2*)((SB)+(rl+8)*66+col) = make_float2(w[4*nt+2],w[4*nt+3]); } } while(0)
#define SCR_ADD(SB) do { _Pragma("unroll") for (int nt=0;nt<8;nt++){ int col=8*nt+2*tig; \
  float2 pa=*(const float2*)((SB)+rl*66+col), pb=*(const float2*)((SB)+(rl+8)*66+col); \
  w[4*nt]+=pa.x; w[4*nt+1]+=pa.y; w[4*nt+2]+=pb.x; w[4*nt+3]+=pb.y; } } while(0)
#define SCR_SUM2() do { _Pragma("unroll") for (int nt=0;nt<8;nt++){ int col=8*nt+2*tig; \
  float2 a0=*(const float2*)(scrA+rl*66+col), a1=*(const float2*)(scrA+(rl+8)*66+col); \
  float2 b0v=*(const float2*)(scrB+rl*66+col), b1v=*(const float2*)(scrB+(rl+8)*66+col); \
  w[4*nt]=a0.x+b0v.x; w[4*nt+1]=a0.y+b0v.y; w[4*nt+2]=a1.x+b1v.x; w[4*nt+3]=a1.y+b1v.y; } } while(0)
// 2-round butterfly: result = full w in every warp
#define EXCHANGE() do { \
  if (q == 1) SCR_ST(scrA); \
  if (q == 3) SCR_ST(scrB); \
  __syncthreads(); \
  if (q == 0) { SCR_ADD(scrA); SCR_ST(scrA); } \
  if (q == 2) { SCR_ADD(scrB); SCR_ST(scrB); } \
  __syncthreads(); \
  SCR_SUM2(); } while(0)

#define PACK_A(src) do { _Pragma("unroll") for (int j=0;j<4;j++){ \
  pkhl((src)[8*j],  (src)[8*j+1], aH[4*j],  aL[4*j]); \
  pkhl((src)[8*j+2],(src)[8*j+3], aH[4*j+1],aL[4*j+1]); \
  pkhl((src)[8*j+4],(src)[8*j+5], aH[4*j+2],aL[4*j+2]); \
  pkhl((src)[8*j+6],(src)[8*j+7], aH[4*j+3],aL[4*j+3]); } } while(0)

__global__ __launch_bounds__(TPB, 1)
void irb(const float* __restrict__ gx,  const float* __restrict__ gu,
         const float* __restrict__ glp, const float* __restrict__ gve,
         const float* __restrict__ gW1x,const float* __restrict__ gW1u,
         const float* __restrict__ gb1, const float* __restrict__ gW2,
         const float* __restrict__ gb2, float* __restrict__ out, int B)
{
  extern __shared__ char sm[];
  const uint32_t smb = s2u(sm);
  const int tid = threadIdx.x, lane = tid & 31, warp = tid >> 5;
  const int q = warp >> 2, wr = warp & 3, g = lane >> 2, tig = lane & 3;
  const int rl = wr*16 + g;                 // local row 0..63
  const int growl = blockIdx.x*64 + rl;
  const int hq = q*64;                      // h-quarter base
  float* scrA = (float*)(sm + O_SCRA);
  float* scrB = (float*)(sm + O_SCRB);
  float* sB1 = (float*)(sm + O_B1);

  __nv_bfloat16* s16 = (__nv_bfloat16*)sm;
  for (int i = tid; i < 256*64; i += TPB) {          // W2 [H][D]
    int h = i >> 6, d = i & 63, o = swo(h, 2*d) >> 1;
    float v = gW2[i];
    __nv_bfloat16 bh = __float2bfloat16_rn(v);
    s16[(O_W2H>>1)+o] = bh;
    s16[(O_W2L>>1)+o] = __float2bfloat16_rn(v - __bfloat162float(bh));
  }
  for (int i = tid; i < 64*256; i += TPB) {          // W1u, W1x [D][H] -> [h][d]
    int d = i >> 8, h = i & 255, o = swo(h, 2*d) >> 1;
    float v = gW1u[i];
    __nv_bfloat16 bh = __float2bfloat16_rn(v);
    s16[(O_W1UH>>1)+o] = bh;
    s16[(O_W1UL>>1)+o] = __float2bfloat16_rn(v - __bfloat162float(bh));
    float w_ = gW1x[i];
    __nv_bfloat16 wh = __float2bfloat16_rn(w_);
    s16[(O_X>>1)+o] = wh;
    s16[(O_W1XL>>1)+o] = __float2bfloat16_rn(w_ - __bfloat162float(wh));
  }
  for (int i = tid; i < 256; i += TPB) sB1[i] = gb1[i];
  {
    const float4* xs = (const float4*)(gx + (size_t)blockIdx.x*64*64);
    float4* xo = (float4*)(out + (size_t)blockIdx.x*64*64);
    for (int i = tid; i < 64*16; i += TPB) xo[i] = xs[i];
  }

  // xu A-fragments hi/lo, k = [x | u] (transient; used only for z)
  uint32_t xh[32], xl[32];
  #pragma unroll
  for (int j = 0; j < 8; j++) {
    const float* src = (j < 4 ? gx : gu) + (size_t)growl*64 + 16*(j & 3);
    float2 v0 = *(const float2*)(src + 2*tig);
    float2 v1 = *(const float2*)(src + 512 + 2*tig);
    float2 v2 = *(const float2*)(src + 8 + 2*tig);
    float2 v3 = *(const float2*)(src + 512 + 8 + 2*tig);
    pkhl(v0.x,v0.y, xh[4*j],  xl[4*j]);   pkhl(v1.x,v1.y, xh[4*j+1],xl[4*j+1]);
    pkhl(v2.x,v2.y, xh[4*j+2],xl[4*j+2]); pkhl(v3.x,v3.y, xh[4*j+3],xl[4*j+3]);
  }
  __syncthreads();

  const int prow = (lane&7) + ((lane>>4)&1)*8, pcol = ((lane>>3)&1)*16;
  const int trow = (lane&7) + ((lane>>3)&1)*8, tcol = ((lane>>4)&1)*16;

  // z-GEMM into p[] (own 64-h quarter)
  float p[32];
  #pragma unroll
  for (int i = 0; i < 32; i++) p[i] = 0.f;
  #pragma unroll
  for (int j = 0; j < 8; j++) {
    uint32_t bh_ = smb + (j < 4 ? O_X    : O_W1UH);
    uint32_t bl_ = smb + (j < 4 ? O_W1XL : O_W1UL);
    int jb = 32*(j & 3);
    #pragma unroll
    for (int tp = 0; tp < 4; tp++) {
      int hb = hq + 16*tp;
      uint32_t b0,b1r,b2,b3,c0,c1,c2,c3;
      LDSM(b0,b1r,b2,b3, bh_ + swo(hb+prow, jb+pcol));
      LDSM(c0,c1,c2,c3, bl_ + swo(hb+prow, jb+pcol));
      MMA(p+8*tp,  xh+4*j,b0,b1r); MMA(p+8*tp+4,xh+4*j,b2,b3);
      MMA(p+8*tp,  xl+4*j,b0,b1r); MMA(p+8*tp+4,xl+4*j,b2,b3);
      MMA(p+8*tp,  xh+4*j,c0,c1);  MMA(p+8*tp+4,xh+4*j,c2,c3);
    }
  }
  __syncthreads();   // z done; W1x region becomes s slab

  // ve in C-fragment layout (loaded after z to limit reg pressure)
  float vC[32];
  {
    const float* v0 = gve + (size_t)growl*64;
    #pragma unroll
    for (int nt = 0; nt < 8; nt++) {
      float2 a = *(const float2*)(v0 + 8*nt + 2*tig);
      float2 b = *(const float2*)(v0 + 512 + 8*nt + 2*tig);
      vC[4*nt] = a.x; vC[4*nt+1] = a.y; vC[4*nt+2] = b.x; vC[4*nt+3] = b.y;
    }
  }

  // activation: s -> slab [i*512+tid] fp32 (conflict-free), ha -> p[]
  float* sS = (float*)(sm + O_X);
  #pragma unroll
  for (int nt = 0; nt < 8; nt++) {
    int col = hq + 8*nt + 2*tig;
    float2 bv = *(const float2*)(sB1 + col);
    #pragma unroll
    for (int e = 0; e < 4; e++) {
      float zz = p[4*nt+e] + ((e & 1) ? bv.y : bv.x);
      float ex = __expf(zz);
      sS[(4*nt+e)*512 + tid] = zz > 0.f ? 1.f : ex;
      p[4*nt+e] = zz > 0.f ? zz : ex - 1.f;
    }
  }

  // g-GEMM (A = ha in p[]), 4-way split-K -> butterfly
  float w[32];
  uint32_t aH[16], aL[16];
  #pragma unroll
  for (int i = 0; i < 32; i++) w[i] = 0.f;
  #pragma unroll
  for (int j2 = 0; j2 < 4; j2++) {
    uint32_t yh4[4], yl4[4];
    pkhl(p[8*j2],  p[8*j2+1], yh4[0], yl4[0]); pkhl(p[8*j2+2],p[8*j2+3], yh4[1], yl4[1]);
    pkhl(p[8*j2+4],p[8*j2+5], yh4[2], yl4[2]); pkhl(p[8*j2+6],p[8*j2+7], yh4[3], yl4[3]);
    WCHUNK(O_W2H, O_W2L, j2, yh4, yl4);
  }
  EXCHANGE();
  if (q == 0) {      // v = u + g + b2
    const float* u0 = gu + (size_t)growl*64;
    float* vo = out + (size_t)B*64 + (size_t)growl*64;
    #pragma unroll
    for (int nt = 0; nt < 8; nt++) {
      int col = 8*nt + 2*tig;
      float2 ua = *(const float2*)(u0 + col);
      float2 ub = *(const float2*)(u0 + 512 + col);
      float2 bb = *(const float2*)(gb2 + col);
      *(float2*)(vo + col)       = make_float2(ua.x + w[4*nt]   + bb.x, ua.y + w[4*nt+1] + bb.y);
      *(float2*)(vo + 512 + col) = make_float2(ub.x + w[4*nt+2] + bb.x, ub.y + w[4*nt+3] + bb.y);
    }
  }
  __syncthreads();

  // p1 = ve @ W2^T
  PACK_A(vC);
  PGEMM();

  // power series
  float lgdl = 0.f, lgdh = 0.f;
  #pragma unroll 1
  for (int k = 1; k <= NPS; k++) {
    #pragma unroll
    for (int i = 0; i < 32; i++) w[i] = 0.f;
    #pragma unroll
    for (int j2 = 0; j2 < 4; j2++) {
      float y8[8];
      #pragma unroll
      for (int e = 0; e < 8; e++) y8[e] = p[8*j2+e] * sS[(8*j2+e)*512 + tid];
      uint32_t yh4[4], yl4[4];
      pkhl(y8[0],y8[1], yh4[0], yl4[0]); pkhl(y8[2],y8[3], yh4[1], yl4[1]);
      pkhl(y8[4],y8[5], yh4[2], yl4[2]); pkhl(y8[6],y8[7], yh4[3], yl4[3]);
      WCHUNK(O_W1UH, O_W1UL, j2, yh4, yl4);
    }
    EXCHANGE();                         // every warp: full w
    if (q == 0) {
      float dl = 0.f, dh = 0.f;
      #pragma unroll
      for (int nt = 0; nt < 8; nt++) {
        dl = fmaf(w[4*nt],   vC[4*nt],   fmaf(w[4*nt+1], vC[4*nt+1], dl));
        dh = fmaf(w[4*nt+2], vC[4*nt+2], fmaf(w[4*nt+3], vC[4*nt+3], dh));
      }
      dl += __shfl_xor_sync(0xffffffffu, dl, 1); dl += __shfl_xor_sync(0xffffffffu, dl, 2);
      dh += __shfl_xor_sync(0xffffffffu, dh, 1); dh += __shfl_xor_sync(0xffffffffu, dh, 2);
      float ck = ((k & 1) ? 1.f : -1.f) / (float)k;
      lgdl = fmaf(ck, dl, lgdl); lgdh = fmaf(ck, dh, lgdh);
    }
    if (k < NPS) {
      PACK_A(w);
      PGEMM();
    }
  }

  if (q == 0 && tig == 0) {
    out[(size_t)2*B*64 + growl]     = glp[growl]     - lgdl;
    out[(size_t)2*B*64 + growl + 8] = glp[growl + 8] - lgdh;
  }
}

extern "C" void kernel_launch(void* const* d_in, const int* in_sizes, int n_in,
                              void* d_out, int out_size)
{
  const float* gx   = (const float*)d_in[0];
  const float* gu   = (const float*)d_in[1];
  const float* glp  = (const float*)d_in[2];
  const float* gve  = (const float*)d_in[3];
  const float* gW1x = (const float*)d_in[4];
  const float* gW1u = (const float*)d_in[5];
  const float* gb1  = (const float*)d_in[6];
  const float* gW2  = (const float*)d_in[7];
  const float* gb2  = (const float*)d_in[8];
  float* out = (float*)d_out;

  int B = in_sizes[0] / 64;          // 131072
  int grid = B / 64;                 // 2048

  cudaFuncSetAttribute(irb, cudaFuncAttributeMaxDynamicSharedMemorySize, SMEM_TOTAL);
  irb<<<grid, TPB, SMEM_TOTAL>>>(gx, gu, glp, gve, gW1x, gW1u, gb1, gW2, gb2, out, B);
}

// round 15
// speedup vs baseline: 1.4079x; 1.4079x over previous
#include <cuda_runtime.h>
#include <cuda_bf16.h>
#include <cstdint>

#define TPB 256
#define NPS 10
#define O_W1UH 0
#define O_W1UL 32768
#define O_W2H  65536
#define O_W2L  98304
#define O_X    131072
#define O_W1XL 163840
#define O_SCR  198656
#define O_B1   215552
#define SMEM_TOTAL 216576

__device__ __forceinline__ uint32_t s2u(const void* p){
  uint32_t a; asm("{ .reg .u64 t; cvta.to.shared.u64 t,%1; cvt.u32.u64 %0,t; }":"=r"(a):"l"(p)); return a;
}
__device__ __forceinline__ uint32_t pk2(float lo, float hi){
  uint32_t r; asm("cvt.rn.bf16x2.f32 %0,%1,%2;":"=r"(r):"f"(hi),"f"(lo)); return r;
}
__device__ __forceinline__ void pkhl(float a, float b, uint32_t& h, uint32_t& l){
  h = pk2(a, b);
  float ah = __uint_as_float(h << 16), bh = __uint_as_float(h & 0xffff0000u);
  l = pk2(a - ah, b - bh);
}
__device__ __forceinline__ int swo(int r, int cb){ return r*128 + (cb ^ ((r&7)<<4)); }

#define MMA(d,a,b0,b1) asm volatile( \
  "mma.sync.aligned.m16n8k16.row.col.f32.bf16.bf16.f32 {%0,%1,%2,%3},{%4,%5,%6,%7},{%8,%9},{%0,%1,%2,%3};" \
  :"+f"((d)[0]),"+f"((d)[1]),"+f"((d)[2]),"+f"((d)[3]) \
  :"r"((a)[0]),"r"((a)[1]),"r"((a)[2]),"r"((a)[3]),"r"(b0),"r"(b1))
#define LDSM(r0,r1,r2,r3,ad) asm volatile( \
  "ldmatrix.sync.aligned.m8n8.x4.shared.b16 {%0,%1,%2,%3},[%4];" \
  :"=r"(r0),"=r"(r1),"=r"(r2),"=r"(r3):"r"(ad))
#define LDSMT(r0,r1,r2,r3,ad) asm volatile( \
  "ldmatrix.sync.aligned.m8n8.x4.trans.shared.b16 {%0,%1,%2,%3},[%4];" \
  :"=r"(r0),"=r"(r1),"=r"(r2),"=r"(r3):"r"(ad))

// ---- pipelined p-GEMM: p[m, wg-half 128h] = A(aH/aL,k=64) @ W2^T
// step T: j=T>>3 (k16 chunk), tp=T&7 (16-h tile); B-frags for T+1 loaded before T's MMAs
#define PH_ADDR(T) (smb+O_W2H+swo(wg*128+16*((T)&7)+prow, 32*((T)>>3)+pcol))
#define PL_ADDR(T) (smb+O_W2L+swo(wg*128+16*((T)&7)+prow, 32*((T)>>3)+pcol))
#define PGEMM() do { \
  _Pragma("unroll") for (int i_=0;i_<64;i_++) p[i_]=0.f; \
  uint32_t fE[8], fO[8]; \
  LDSM(fE[0],fE[1],fE[2],fE[3], PH_ADDR(0)); \
  LDSM(fE[4],fE[5],fE[6],fE[7], PL_ADDR(0)); \
  _Pragma("unroll") for (int t_=0;t_<32;t_++){ \
    uint32_t* cu_=(t_&1)?fO:fE; uint32_t* nx_=(t_&1)?fE:fO; \
    if (t_<31){ LDSM(nx_[0],nx_[1],nx_[2],nx_[3], PH_ADDR(t_+1)); \
                LDSM(nx_[4],nx_[5],nx_[6],nx_[7], PL_ADDR(t_+1)); } \
    int j_=t_>>3; float* q_=p+8*(t_&7); \
    MMA(q_,  aH+4*j_,cu_[0],cu_[1]); MMA(q_+4,aH+4*j_,cu_[2],cu_[3]); \
    MMA(q_,  aL+4*j_,cu_[0],cu_[1]); MMA(q_+4,aL+4*j_,cu_[2],cu_[3]); \
    MMA(q_,  aH+4*j_,cu_[4],cu_[5]); MMA(q_+4,aH+4*j_,cu_[6],cu_[7]); \
  } } while(0)

// ---- pipelined w-GEMM: w[m,64d] partial over wg's 128 h (trans B)
// step T: j2=T>>2 (16-h k-chunk), np=T&3 (d-tile pair); A re-packed at np==0
#define WADDR(T,BO) (smb+(BO)+swo(wg*128+16*((T)>>2)+trow, 32*((T)&3)+tcol))
#define WGEMM_PIPE(BH,BL,YEXPR) do { \
  _Pragma("unroll") for (int i_=0;i_<32;i_++) w[i_]=0.f; \
  uint32_t gE[8], gO[8], yh4[4], yl4[4]; \
  LDSMT(gE[0],gE[1],gE[2],gE[3], WADDR(0,BH)); \
  LDSMT(gE[4],gE[5],gE[6],gE[7], WADDR(0,BL)); \
  _Pragma("unroll") for (int t_=0;t_<32;t_++){ \
    uint32_t* cu_=(t_&1)?gO:gE; uint32_t* nx_=(t_&1)?gE:gO; \
    if (t_<31){ LDSMT(nx_[0],nx_[1],nx_[2],nx_[3], WADDR(t_+1,BH)); \
                LDSMT(nx_[4],nx_[5],nx_[6],nx_[7], WADDR(t_+1,BL)); } \
    if ((t_&3)==0){ int j2_=t_>>2; float y8_[8]; \
      _Pragma("unroll") for (int e_=0;e_<8;e_++) y8_[e_]=(YEXPR); \
      pkhl(y8_[0],y8_[1],yh4[0],yl4[0]); pkhl(y8_[2],y8_[3],yh4[1],yl4[1]); \
      pkhl(y8_[4],y8_[5],yh4[2],yl4[2]); pkhl(y8_[6],y8_[7],yh4[3],yl4[3]); } \
    float* q_=w+8*(t_&3); \
    MMA(q_,  yh4,cu_[0],cu_[1]); MMA(q_+4,yh4,cu_[2],cu_[3]); \
    MMA(q_,  yl4,cu_[0],cu_[1]); MMA(q_+4,yl4,cu_[2],cu_[3]); \
    MMA(q_,  yh4,cu_[4],cu_[5]); MMA(q_+4,yh4,cu_[6],cu_[7]); \
  } } while(0)

#define SCR_ST() do { _Pragma("unroll") for (int nt=0;nt<8;nt++){ int col=8*nt+2*tig; \
  *(float2*)(scr+rl*66+col)     = make_float2(w[4*nt],  w[4*nt+1]); \
  *(float2*)(scr+(rl+8)*66+col) = make_float2(w[4*nt+2],w[4*nt+3]); } } while(0)
#define SCR_ADD() do { _Pragma("unroll") for (int nt=0;nt<8;nt++){ int col=8*nt+2*tig; \
  float2 pa=*(const float2*)(scr+rl*66+col), pb=*(const float2*)(scr+(rl+8)*66+col); \
  w[4*nt]+=pa.x; w[4*nt+1]+=pa.y; w[4*nt+2]+=pb.x; w[4*nt+3]+=pb.y; } } while(0)
#define SCR_LD() do { _Pragma("unroll") for (int nt=0;nt<8;nt++){ int col=8*nt+2*tig; \
  float2 pa=*(const float2*)(scr+rl*66+col), pb=*(const float2*)(scr+(rl+8)*66+col); \
  w[4*nt]=pa.x; w[4*nt+1]=pa.y; w[4*nt+2]=pb.x; w[4*nt+3]=pb.y; } } while(0)
#define PACK_A(src) do { _Pragma("unroll") for (int j=0;j<4;j++){ \
  pkhl((src)[8*j],  (src)[8*j+1], aH[4*j],  aL[4*j]); \
  pkhl((src)[8*j+2],(src)[8*j+3], aH[4*j+1],aL[4*j+1]); \
  pkhl((src)[8*j+4],(src)[8*j+5], aH[4*j+2],aL[4*j+2]); \
  pkhl((src)[8*j+6],(src)[8*j+7], aH[4*j+3],aL[4*j+3]); } } while(0)

__global__ __launch_bounds__(TPB, 1)
void irb(const float* __restrict__ gx,  const float* __restrict__ gu,
         const float* __restrict__ glp, const float* __restrict__ gve,
         const float* __restrict__ gW1x,const float* __restrict__ gW1u,
         const float* __restrict__ gb1, const float* __restrict__ gW2,
         const float* __restrict__ gb2, float* __restrict__ out, int B)
{
  extern __shared__ char sm[];
  const uint32_t smb = s2u(sm);
  const int tid = threadIdx.x, lane = tid & 31, warp = tid >> 5;
  const int wg = warp >> 2, wr = warp & 3, g = lane >> 2, tig = lane & 3;
  const int rl = wr*16 + g;
  const int growl = blockIdx.x*64 + rl;
  float* scr = (float*)(sm + O_SCR);
  float* sB1 = (float*)(sm + O_B1);

  __nv_bfloat16* s16 = (__nv_bfloat16*)sm;
  for (int i = tid; i < 256*64; i += TPB) {          // W2 [H][D]
    int h = i >> 6, d = i & 63, o = swo(h, 2*d) >> 1;
    float v = gW2[i];
    __nv_bfloat16 bh = __float2bfloat16_rn(v);
    s16[(O_W2H>>1)+o] = bh;
    s16[(O_W2L>>1)+o] = __float2bfloat16_rn(v - __bfloat162float(bh));
  }
  for (int i = tid; i < 64*256; i += TPB) {          // W1u, W1x [D][H] -> [h][d]
    int d = i >> 8, h = i & 255, o = swo(h, 2*d) >> 1;
    float v = gW1u[i];
    __nv_bfloat16 bh = __float2bfloat16_rn(v);
    s16[(O_W1UH>>1)+o] = bh;
    s16[(O_W1UL>>1)+o] = __float2bfloat16_rn(v - __bfloat162float(bh));
    float w_ = gW1x[i];
    __nv_bfloat16 wh = __float2bfloat16_rn(w_);
    s16[(O_X>>1)+o] = wh;
    s16[(O_W1XL>>1)+o] = __float2bfloat16_rn(w_ - __bfloat162float(wh));
  }
  for (int i = tid; i < 256; i += TPB) sB1[i] = gb1[i];
  {
    const float4* xs = (const float4*)(gx + (size_t)blockIdx.x*64*64);
    float4* xo = (float4*)(out + (size_t)blockIdx.x*64*64);
    for (int i = tid; i < 64*16; i += TPB) xo[i] = xs[i];
  }

  // xu A-fragments hi/lo, k = [x | u]
  uint32_t xh[32], xl[32];
  #pragma unroll
  for (int j = 0; j < 8; j++) {
    const float* src = (j < 4 ? gx : gu) + (size_t)growl*64 + 16*(j & 3);
    float2 v0 = *(const float2*)(src + 2*tig);
    float2 v1 = *(const float2*)(src + 512 + 2*tig);
    float2 v2 = *(const float2*)(src + 8 + 2*tig);
    float2 v3 = *(const float2*)(src + 512 + 8 + 2*tig);
    pkhl(v0.x,v0.y, xh[4*j],  xl[4*j]);   pkhl(v1.x,v1.y, xh[4*j+1],xl[4*j+1]);
    pkhl(v2.x,v2.y, xh[4*j+2],xl[4*j+2]); pkhl(v3.x,v3.y, xh[4*j+3],xl[4*j+3]);
  }
  __syncthreads();

  const int prow = (lane&7) + ((lane>>4)&1)*8, pcol = ((lane>>3)&1)*16;
  const int trow = (lane&7) + ((lane>>3)&1)*8, tcol = ((lane>>4)&1)*16;

  // z-GEMM into p[]
  float p[64];
  #pragma unroll
  for (int i = 0; i < 64; i++) p[i] = 0.f;
  #pragma unroll
  for (int j = 0; j < 8; j++) {
    uint32_t bh_ = smb + (j < 4 ? O_X    : O_W1UH);
    uint32_t bl_ = smb + (j < 4 ? O_W1XL : O_W1UL);
    int jb = 32*(j & 3);
    #pragma unroll
    for (int tp = 0; tp < 8; tp++) {
      int hb = wg*128 + 16*tp;
      uint32_t b0,b1r,b2,b3,c0,c1,c2,c3;
      LDSM(b0,b1r,b2,b3, bh_ + swo(hb+prow, jb+pcol));
      LDSM(c0,c1,c2,c3, bl_ + swo(hb+prow, jb+pcol));
      MMA(p+8*tp,  xh+4*j,b0,b1r); MMA(p+8*tp+4,xh+4*j,b2,b3);
      MMA(p+8*tp,  xl+4*j,b0,b1r); MMA(p+8*tp+4,xl+4*j,b2,b3);
      MMA(p+8*tp,  xh+4*j,c0,c1);  MMA(p+8*tp+4,xh+4*j,c2,c3);
    }
  }
  __syncthreads();   // z done; W1x region becomes s slab

  // activation: s -> per-thread slab, ha -> p[]
  float* sS = (float*)(sm + O_X) + tid*66;
  #pragma unroll
  for (int nt = 0; nt < 16; nt++) {
    int col = wg*128 + 8*nt + 2*tig;
    float2 bv = *(const float2*)(sB1 + col);
    float s4[4];
    #pragma unroll
    for (int e = 0; e < 4; e++) {
      float zz = p[4*nt+e] + ((e & 1) ? bv.y : bv.x);
      float ex = __expf(zz);
      s4[e] = zz > 0.f ? 1.f : ex;
      p[4*nt+e] = zz > 0.f ? zz : ex - 1.f;
    }
    *(float2*)(sS + 4*nt)     = make_float2(s4[0], s4[1]);
    *(float2*)(sS + 4*nt + 2) = make_float2(s4[2], s4[3]);
  }

  // g-GEMM (A = ha in p[]), split-K over h-halves
  float w[32];
  uint32_t aH[16], aL[16];
  WGEMM_PIPE(O_W2H, O_W2L, p[8*j2_+e_]);
  if (wg == 1) SCR_ST();
  __syncthreads();
  if (wg == 0) {      // v = u + g + b2
    SCR_ADD();
    const float* u0 = gu + (size_t)growl*64;
    float* vo = out + (size_t)B*64 + (size_t)growl*64;
    #pragma unroll
    for (int nt = 0; nt < 8; nt++) {
      int col = 8*nt + 2*tig;
      float2 ua = *(const float2*)(u0 + col);
      float2 ub = *(const float2*)(u0 + 512 + col);
      float2 bb = *(const float2*)(gb2 + col);
      *(float2*)(vo + col)       = make_float2(ua.x + w[4*nt]   + bb.x, ua.y + w[4*nt+1] + bb.y);
      *(float2*)(vo + 512 + col) = make_float2(ub.x + w[4*nt+2] + bb.x, ub.y + w[4*nt+3] + bb.y);
    }
  }
  __syncthreads();

  // p1 = ve @ W2^T (ve loaded transiently in C-frag layout)
  {
    float vC[32];
    const float* v0 = gve + (size_t)growl*64;
    #pragma unroll
    for (int nt = 0; nt < 8; nt++) {
      float2 a = *(const float2*)(v0 + 8*nt + 2*tig);
      float2 b = *(const float2*)(v0 + 512 + 8*nt + 2*tig);
      vC[4*nt] = a.x; vC[4*nt+1] = a.y; vC[4*nt+2] = b.x; vC[4*nt+3] = b.y;
    }
    PACK_A(vC);
  }
  PGEMM();

  // power series
  float lgdl = 0.f, lgdh = 0.f;
  #pragma unroll 1
  for (int k = 1; k <= NPS; k++) {
    WGEMM_PIPE(O_W1UH, O_W1UL, p[8*j2_+e_] * sS[8*j2_+e_]);
    if (wg == 1) SCR_ST();
    __syncthreads();
    if (wg == 0) {
      SCR_ADD();
      float dl = 0.f, dh = 0.f;
      const float* v0 = gve + (size_t)growl*64;
      #pragma unroll
      for (int nt = 0; nt < 8; nt++) {
        float2 a = *(const float2*)(v0 + 8*nt + 2*tig);
        float2 b = *(const float2*)(v0 + 512 + 8*nt + 2*tig);
        dl = fmaf(w[4*nt],   a.x, fmaf(w[4*nt+1], a.y, dl));
        dh = fmaf(w[4*nt+2], b.x, fmaf(w[4*nt+3], b.y, dh));
      }
      dl += __shfl_xor_sync(0xffffffffu, dl, 1); dl += __shfl_xor_sync(0xffffffffu, dl, 2);
      dh += __shfl_xor_sync(0xffffffffu, dh, 1); dh += __shfl_xor_sync(0xffffffffu, dh, 2);
      float ck = ((k & 1) ? 1.f : -1.f) / (float)k;
      lgdl = fmaf(ck, dl, lgdl); lgdh = fmaf(ck, dh, lgdh);
    }
    if (k < NPS) {
      if (wg == 0) SCR_ST();
      __syncthreads();
      if (wg == 1) SCR_LD();
      PACK_A(w);
      PGEMM();
    }
  }

  if (wg == 0 && tig == 0) {
    out[(size_t)2*B*64 + growl]     = glp[growl]     - lgdl;
    out[(size_t)2*B*64 + growl + 8] = glp[growl + 8] - lgdh;
  }
}

extern "C" void kernel_launch(void* const* d_in, const int* in_sizes, int n_in,
                              void* d_out, int out_size)
{
  const float* gx   = (const float*)d_in[0];
  const float* gu   = (const float*)d_in[1];
  const float* glp  = (const float*)d_in[2];
  const float* gve  = (const float*)d_in[3];
  const float* gW1x = (const float*)d_in[4];
  const float* gW1u = (const float*)d_in[5];
  const float* gb1  = (const float*)d_in[6];
  const float* gW2  = (const float*)d_in[7];
  const float* gb2  = (const float*)d_in[8];
  float* out = (float*)d_out;

  int B = in_sizes[0] / 64;          // 131072
  int grid = B / 64;                 // 2048

  cudaFuncSetAttribute(irb, cudaFuncAttributeMaxDynamicSharedMemorySize, SMEM_TOTAL);
  irb<<<grid, TPB, SMEM_TOTAL>>>(gx, gu, glp, gve, gW1x, gW1u, gb1, gW2, gb2, out, B);
}

// round 16
// speedup vs baseline: 1.7954x; 1.2753x over previous
#include <cuda_runtime.h>
#include <cuda_fp16.h>
#include <cstdint>

#define TPB 256
#define NPS 10
// smem: W1u-hi 32K | W2-hi 32K | W1x-hi 32K (-> s slab 67.5K) | scr | b1
#define O_W1UH 0
#define O_W2H  32768
#define O_X    65536
#define O_SCR  133120
#define O_B1   150016
#define SMEM_TOTAL 151040

__device__ __forceinline__ uint32_t s2u(const void* p){
  uint32_t a; asm("{ .reg .u64 t; cvta.to.shared.u64 t,%1; cvt.u32.u64 %0,t; }":"=r"(a):"l"(p)); return a;
}
__device__ __forceinline__ uint32_t pk2(float a, float b){
  __half2 h = __floats2half2_rn(a, b);
  return *(uint32_t*)&h;
}
__device__ __forceinline__ void pkhl(float a, float b, uint32_t& h, uint32_t& l){
  __half ha = __float2half_rn(a), hb = __float2half_rn(b);
  __half2 hp = __halves2half2(ha, hb);
  h = *(uint32_t*)&hp;
  l = pk2(a - __half2float(ha), b - __half2float(hb));
}
__device__ __forceinline__ int swo(int r, int cb){ return r*128 + (cb ^ ((r&7)<<4)); }

#define MMA(d,a,b0,b1) asm volatile( \
  "mma.sync.aligned.m16n8k16.row.col.f32.f16.f16.f32 {%0,%1,%2,%3},{%4,%5,%6,%7},{%8,%9},{%0,%1,%2,%3};" \
  :"+f"((d)[0]),"+f"((d)[1]),"+f"((d)[2]),"+f"((d)[3]) \
  :"r"((a)[0]),"r"((a)[1]),"r"((a)[2]),"r"((a)[3]),"r"(b0),"r"(b1))
#define LDSM(r0,r1,r2,r3,ad) asm volatile( \
  "ldmatrix.sync.aligned.m8n8.x4.shared.b16 {%0,%1,%2,%3},[%4];" \
  :"=r"(r0),"=r"(r1),"=r"(r2),"=r"(r3):"r"(ad))
#define LDSMT(r0,r1,r2,r3,ad) asm volatile( \
  "ldmatrix.sync.aligned.m8n8.x4.trans.shared.b16 {%0,%1,%2,%3},[%4];" \
  :"=r"(r0),"=r"(r1),"=r"(r2),"=r"(r3):"r"(ad))

// p[m, wg-half 128h] = A(aH/aL, k=64) @ W2^T  — hi weights only, 4 MMAs/tile-chunk
#define PGEMM() do { \
  _Pragma("unroll") for (int i_=0;i_<64;i_++) p[i_]=0.f; \
  _Pragma("unroll") for (int j_=0;j_<4;j_++){ \
    _Pragma("unroll") for (int tp_=0;tp_<8;tp_++){ int hb_=wg*128+16*tp_; \
      uint32_t b0,b1r,b2,b3; \
      LDSM(b0,b1r,b2,b3, smb+O_W2H+swo(hb_+prow,32*j_+pcol)); \
      MMA(p+8*tp_,  aH+4*j_,b0,b1r); MMA(p+8*tp_+4,aH+4*j_,b2,b3); \
      MMA(p+8*tp_,  aL+4*j_,b0,b1r); MMA(p+8*tp_+4,aL+4*j_,b2,b3); \
  } } } while(0)

// one k-chunk (16 h) of the d=64 GEMM (trans B), hi weights only
#define WCHUNK(BH,J2,YH,YL) do { int kb_=wg*128+16*(J2); \
  _Pragma("unroll") for (int np_=0;np_<4;np_++){ \
    uint32_t b0,b1r,b2,b3; \
    LDSMT(b0,b1r,b2,b3, smb+(BH)+swo(kb_+trow,32*np_+tcol)); \
    MMA(w+8*np_,  YH,b0,b1r); MMA(w+8*np_+4,YH,b2,b3); \
    MMA(w+8*np_,  YL,b0,b1r); MMA(w+8*np_+4,YL,b2,b3); \
  } } while(0)

#define SCR_ST() do { _Pragma("unroll") for (int nt=0;nt<8;nt++){ int col=8*nt+2*tig; \
  *(float2*)(scr+rl*66+col)     = make_float2(w[4*nt],  w[4*nt+1]); \
  *(float2*)(scr+(rl+8)*66+col) = make_float2(w[4*nt+2],w[4*nt+3]); } } while(0)
#define SCR_ADD() do { _Pragma("unroll") for (int nt=0;nt<8;nt++){ int col=8*nt+2*tig; \
  float2 pa=*(const float2*)(scr+rl*66+col), pb=*(const float2*)(scr+(rl+8)*66+col); \
  w[4*nt]+=pa.x; w[4*nt+1]+=pa.y; w[4*nt+2]+=pb.x; w[4*nt+3]+=pb.y; } } while(0)
#define SCR_LD() do { _Pragma("unroll") for (int nt=0;nt<8;nt++){ int col=8*nt+2*tig; \
  float2 pa=*(const float2*)(scr+rl*66+col), pb=*(const float2*)(scr+(rl+8)*66+col); \
  w[4*nt]=pa.x; w[4*nt+1]=pa.y; w[4*nt+2]=pb.x; w[4*nt+3]=pb.y; } } while(0)
#define PACK_A(src) do { _Pragma("unroll") for (int j=0;j<4;j++){ \
  pkhl((src)[8*j],  (src)[8*j+1], aH[4*j],  aL[4*j]); \
  pkhl((src)[8*j+2],(src)[8*j+3], aH[4*j+1],aL[4*j+1]); \
  pkhl((src)[8*j+4],(src)[8*j+5], aH[4*j+2],aL[4*j+2]); \
  pkhl((src)[8*j+6],(src)[8*j+7], aH[4*j+3],aL[4*j+3]); } } while(0)

__global__ __launch_bounds__(TPB, 1)
void irb(const float* __restrict__ gx,  const float* __restrict__ gu,
         const float* __restrict__ glp, const float* __restrict__ gve,
         const float* __restrict__ gW1x,const float* __restrict__ gW1u,
         const float* __restrict__ gb1, const float* __restrict__ gW2,
         const float* __restrict__ gb2, float* __restrict__ out, int B)
{
  extern __shared__ char sm[];
  const uint32_t smb = s2u(sm);
  const int tid = threadIdx.x, lane = tid & 31, warp = tid >> 5;
  const int wg = warp >> 2, wr = warp & 3, g = lane >> 2, tig = lane & 3;
  const int rl = wr*16 + g;
  const int growl = blockIdx.x*64 + rl;
  float* scr = (float*)(sm + O_SCR);
  float* sB1 = (float*)(sm + O_B1);

  // weights -> smem fp16 hi only, [h][d] 128B rows, XOR swizzle
  __half* s16 = (__half*)sm;
  for (int i = tid; i < 256*64; i += TPB) {          // W2 [H][D]
    int h = i >> 6, d = i & 63, o = swo(h, 2*d) >> 1;
    s16[(O_W2H>>1)+o] = __float2half_rn(gW2[i]);
  }
  for (int i = tid; i < 64*256; i += TPB) {          // W1u, W1x [D][H] -> [h][d]
    int d = i >> 8, h = i & 255, o = swo(h, 2*d) >> 1;
    s16[(O_W1UH>>1)+o] = __float2half_rn(gW1u[i]);
    s16[(O_X>>1)+o]    = __float2half_rn(gW1x[i]);
  }
  for (int i = tid; i < 256; i += TPB) sB1[i] = gb1[i];
  {
    const float4* xs = (const float4*)(gx + (size_t)blockIdx.x*64*64);
    float4* xo = (float4*)(out + (size_t)blockIdx.x*64*64);
    for (int i = tid; i < 64*16; i += TPB) xo[i] = xs[i];
  }

  // ve in C-fragment layout
  float vC[32];
  {
    const float* v0 = gve + (size_t)growl*64;
    #pragma unroll
    for (int nt = 0; nt < 8; nt++) {
      float2 a = *(const float2*)(v0 + 8*nt + 2*tig);
      float2 b = *(const float2*)(v0 + 512 + 8*nt + 2*tig);
      vC[4*nt] = a.x; vC[4*nt+1] = a.y; vC[4*nt+2] = b.x; vC[4*nt+3] = b.y;
    }
  }
  // xu A-fragments hi/lo (fp16 split), k = [x | u]
  uint32_t xh[32], xl[32];
  #pragma unroll
  for (int j = 0; j < 8; j++) {
    const float* src = (j < 4 ? gx : gu) + (size_t)growl*64 + 16*(j & 3);
    float2 v0 = *(const float2*)(src + 2*tig);
    float2 v1 = *(const float2*)(src + 512 + 2*tig);
    float2 v2 = *(const float2*)(src + 8 + 2*tig);
    float2 v3 = *(const float2*)(src + 512 + 8 + 2*tig);
    pkhl(v0.x,v0.y, xh[4*j],  xl[4*j]);   pkhl(v1.x,v1.y, xh[4*j+1],xl[4*j+1]);
    pkhl(v2.x,v2.y, xh[4*j+2],xl[4*j+2]); pkhl(v3.x,v3.y, xh[4*j+3],xl[4*j+3]);
  }
  __syncthreads();

  const int prow = (lane&7) + ((lane>>4)&1)*8, pcol = ((lane>>3)&1)*16;
  const int trow = (lane&7) + ((lane>>3)&1)*8, tcol = ((lane>>4)&1)*16;

  // z-GEMM into p[]
  float p[64];
  #pragma unroll
  for (int i = 0; i < 64; i++) p[i] = 0.f;
  #pragma unroll
  for (int j = 0; j < 8; j++) {
    uint32_t bh_ = smb + (j < 4 ? O_X : O_W1UH);
    int jb = 32*(j & 3);
    #pragma unroll
    for (int tp = 0; tp < 8; tp++) {
      int hb = wg*128 + 16*tp;
      uint32_t b0,b1r,b2,b3;
      LDSM(b0,b1r,b2,b3, bh_ + swo(hb+prow, jb+pcol));
      MMA(p+8*tp,  xh+4*j,b0,b1r); MMA(p+8*tp+4,xh+4*j,b2,b3);
      MMA(p+8*tp,  xl+4*j,b0,b1r); MMA(p+8*tp+4,xl+4*j,b2,b3);
    }
  }
  __syncthreads();   // z done; W1x region becomes s slab

  // activation: s -> per-thread slab, ha -> p[]
  float* sS = (float*)(sm + O_X) + tid*66;
  #pragma unroll
  for (int nt = 0; nt < 16; nt++) {
    int col = wg*128 + 8*nt + 2*tig;
    float2 bv = *(const float2*)(sB1 + col);
    float s4[4];
    #pragma unroll
    for (int e = 0; e < 4; e++) {
      float zz = p[4*nt+e] + ((e & 1) ? bv.y : bv.x);
      float ex = __expf(zz);
      s4[e] = zz > 0.f ? 1.f : ex;
      p[4*nt+e] = zz > 0.f ? zz : ex - 1.f;
    }
    *(float2*)(sS + 4*nt)     = make_float2(s4[0], s4[1]);
    *(float2*)(sS + 4*nt + 2) = make_float2(s4[2], s4[3]);
  }

  // g-GEMM (A = ha in p[]), split-K over h-halves
  float w[32];
  uint32_t aH[16], aL[16];
  #pragma unroll
  for (int i = 0; i < 32; i++) w[i] = 0.f;
  #pragma unroll
  for (int j2 = 0; j2 < 8; j2++) {
    uint32_t yh4[4], yl4[4];
    pkhl(p[8*j2],  p[8*j2+1], yh4[0], yl4[0]); pkhl(p[8*j2+2],p[8*j2+3], yh4[1], yl4[1]);
    pkhl(p[8*j2+4],p[8*j2+5], yh4[2], yl4[2]); pkhl(p[8*j2+6],p[8*j2+7], yh4[3], yl4[3]);
    WCHUNK(O_W2H, j2, yh4, yl4);
  }
  if (wg == 1) SCR_ST();
  __syncthreads();
  if (wg == 0) {      // v = u + g + b2
    SCR_ADD();
    const float* u0 = gu + (size_t)growl*64;
    float* vo = out + (size_t)B*64 + (size_t)growl*64;
    #pragma unroll
    for (int nt = 0; nt < 8; nt++) {
      int col = 8*nt + 2*tig;
      float2 ua = *(const float2*)(u0 + col);
      float2 ub = *(const float2*)(u0 + 512 + col);
      float2 bb = *(const float2*)(gb2 + col);
      *(float2*)(vo + col)       = make_float2(ua.x + w[4*nt]   + bb.x, ua.y + w[4*nt+1] + bb.y);
      *(float2*)(vo + 512 + col) = make_float2(ub.x + w[4*nt+2] + bb.x, ub.y + w[4*nt+3] + bb.y);
    }
  }
  __syncthreads();

  // p1 = ve @ W2^T
  PACK_A(vC);
  PGEMM();

  // power series
  float lgdl = 0.f, lgdh = 0.f;
  #pragma unroll 1
  for (int k = 1; k <= NPS; k++) {
    #pragma unroll
    for (int i = 0; i < 32; i++) w[i] = 0.f;
    #pragma unroll
    for (int j2 = 0; j2 < 8; j2++) {
      float2 sa = *(const float2*)(sS + 8*j2);
      float2 sb = *(const float2*)(sS + 8*j2 + 2);
      float2 sc = *(const float2*)(sS + 8*j2 + 4);
      float2 sd = *(const float2*)(sS + 8*j2 + 6);
      uint32_t yh4[4], yl4[4];
      pkhl(p[8*j2]*sa.x,  p[8*j2+1]*sa.y, yh4[0], yl4[0]);
      pkhl(p[8*j2+2]*sb.x,p[8*j2+3]*sb.y, yh4[1], yl4[1]);
      pkhl(p[8*j2+4]*sc.x,p[8*j2+5]*sc.y, yh4[2], yl4[2]);
      pkhl(p[8*j2+6]*sd.x,p[8*j2+7]*sd.y, yh4[3], yl4[3]);
      WCHUNK(O_W1UH, j2, yh4, yl4);
    }
    if (wg == 1) SCR_ST();
    __syncthreads();
    if (wg == 0) {
      SCR_ADD();
      float dl = 0.f, dh = 0.f;
      #pragma unroll
      for (int nt = 0; nt < 8; nt++) {
        dl = fmaf(w[4*nt],   vC[4*nt],   fmaf(w[4*nt+1], vC[4*nt+1], dl));
        dh = fmaf(w[4*nt+2], vC[4*nt+2], fmaf(w[4*nt+3], vC[4*nt+3], dh));
      }
      dl += __shfl_xor_sync(0xffffffffu, dl, 1); dl += __shfl_xor_sync(0xffffffffu, dl, 2);
      dh += __shfl_xor_sync(0xffffffffu, dh, 1); dh += __shfl_xor_sync(0xffffffffu, dh, 2);
      float ck = ((k & 1) ? 1.f : -1.f) / (float)k;
      lgdl = fmaf(ck, dl, lgdl); lgdh = fmaf(ck, dh, lgdh);
    }
    if (k < NPS) {
      if (wg == 0) SCR_ST();
      __syncthreads();
      if (wg == 1) SCR_LD();
      PACK_A(w);
      PGEMM();
    }
  }

  if (wg == 0 && tig == 0) {
    out[(size_t)2*B*64 + growl]     = glp[growl]     - lgdl;
    out[(size_t)2*B*64 + growl + 8] = glp[growl + 8] - lgdh;
  }
}

extern "C" void kernel_launch(void* const* d_in, const int* in_sizes, int n_in,
                              void* d_out, int out_size)
{
  const float* gx   = (const float*)d_in[0];
  const float* gu   = (const float*)d_in[1];
  const float* glp  = (const float*)d_in[2];
  const float* gve  = (const float*)d_in[3];
  const float* gW1x = (const float*)d_in[4];
  const float* gW1u = (const float*)d_in[5];
  const float* gb1  = (const float*)d_in[6];
  const float* gW2  = (const float*)d_in[7];
  const float* gb2  = (const float*)d_in[8];
  float* out = (float*)d_out;

  int B = in_sizes[0] / 64;          // 131072
  int grid = B / 64;                 // 2048

  cudaFuncSetAttribute(irb, cudaFuncAttributeMaxDynamicSharedMemorySize, SMEM_TOTAL);
  irb<<<grid, TPB, SMEM_TOTAL>>>(gx, gu, glp, gve, gW1x, gW1u, gb1, gW2, gb2, out, B);
}